// round 6
// baseline (speedup 1.0000x reference)
#include <cuda_runtime.h>
#include <cuda_bf16.h>

#define NN 50000
#define EE 600000
#define DD 128
#define MTILE 64
#define NT64 782              // ceil(NN/64)
#define GRID_GEMM 296        // 2 CTAs per SM
#define SCAN_BLKS 49          // ceil(NN/1024)

// ---- fused kernel smem (bytes): W hi/lo 64KB + A hi/lo 32KB ----
#define SM_WH 0
#define SM_WL 32768
#define SM_AH 65536
#define SM_AL 81920
#define GEMM_SMEM 98304

// swizzle for 256B-pitch rows: XOR row%8 into 16B-chunk index
#define SW256(o) ((o) ^ ((((unsigned)(o)) >> 4) & 0x70))

typedef unsigned int u32;

// ---------------- scratch ----------------
__device__ float g_bufA[NN * DD];
__device__ float g_bufB[NN * DD];
__device__ int   g_src[EE];
__device__ int   g_dst[EE];
__device__ int   g_col[EE];
__device__ int   g_rowptr[NN + 1];
__device__ int   g_cursor[NN];
__device__ int   g_count[NN];
__device__ float g_invdeg[NN];
__device__ int   g_btot[64];
__device__ int   g_boff[64];
__device__ int   g_tq[3];
__device__ int   g_is64;

// ---------------- helpers ----------------
__device__ __forceinline__ u32 smem_u32(const void* p) {
    u32 a;
    asm("{ .reg .u64 t; cvta.to.shared.u64 t, %1; cvt.u32.u64 %0, t; }" : "=r"(a) : "l"(p));
    return a;
}
__device__ __forceinline__ void ldm4(u32& r0, u32& r1, u32& r2, u32& r3, u32 a) {
    asm volatile("ldmatrix.sync.aligned.m8n8.x4.shared.b16 {%0,%1,%2,%3}, [%4];"
                 : "=r"(r0), "=r"(r1), "=r"(r2), "=r"(r3) : "r"(a));
}
__device__ __forceinline__ void mma_bf16(float* d, const u32* a, u32 b0, u32 b1) {
    asm volatile(
        "mma.sync.aligned.m16n8k16.row.col.f32.bf16.bf16.f32 "
        "{%0,%1,%2,%3}, {%4,%5,%6,%7}, {%8,%9}, {%0,%1,%2,%3};"
        : "+f"(d[0]), "+f"(d[1]), "+f"(d[2]), "+f"(d[3])
        : "r"(a[0]), "r"(a[1]), "r"(a[2]), "r"(a[3]), "r"(b0), "r"(b1));
}
__device__ __forceinline__ u32 pkbf2(float x, float y) {
    __nv_bfloat162 h = __floats2bfloat162_rn(x, y);
    return *(u32*)&h;
}
__device__ __forceinline__ void split4(float4 v, uint2& h, uint2& l) {
    float bx = __bfloat162float(__float2bfloat16_rn(v.x));
    float by = __bfloat162float(__float2bfloat16_rn(v.y));
    float bz = __bfloat162float(__float2bfloat16_rn(v.z));
    float bw = __bfloat162float(__float2bfloat16_rn(v.w));
    h.x = pkbf2(v.x, v.y);           h.y = pkbf2(v.z, v.w);
    l.x = pkbf2(v.x - bx, v.y - by); l.y = pkbf2(v.z - bz, v.w - bw);
}

// ---------------- preprocessing ----------------
__global__ void init_kernel(const unsigned long long* __restrict__ e) {
    int i = blockIdx.x * blockDim.x + threadIdx.x;
    if (i < NN) g_count[i] = 0;
    if (i < 3) g_tq[i] = 0;
    if (i == 3) {
        int ok = 1;
        #pragma unroll
        for (int t = 0; t < 8; t++)
            if (e[t] >= (unsigned long long)NN) ok = 0;
        g_is64 = ok;
    }
}

__global__ void convert_hist_kernel(const void* __restrict__ eptr) {
    int i = blockIdx.x * blockDim.x + threadIdx.x;
    if (i >= EE) return;
    int s, d;
    if (g_is64) {
        const long long* e = (const long long*)eptr;
        s = (int)e[i]; d = (int)e[EE + i];
    } else {
        const int* e = (const int*)eptr;
        s = e[i]; d = e[EE + i];
    }
    g_src[i] = s;
    g_dst[i] = d;
    atomicAdd(&g_count[d], 1);
}

// multi-block scan: (1) per-block exclusive scan + block totals
__global__ void scan1_kernel() {
    __shared__ int wsum[32];
    int tid = threadIdx.x;
    int lane = tid & 31, wid = tid >> 5;
    int idx = blockIdx.x * 1024 + tid;
    int v = (idx < NN) ? g_count[idx] : 0;
    int s = v;
    #pragma unroll
    for (int o = 1; o < 32; o <<= 1) {
        int t = __shfl_up_sync(0xffffffffu, s, o);
        if (lane >= o) s += t;
    }
    if (lane == 31) wsum[wid] = s;
    __syncthreads();
    if (wid == 0) {
        int w = wsum[lane];
        #pragma unroll
        for (int o = 1; o < 32; o <<= 1) {
            int t = __shfl_up_sync(0xffffffffu, w, o);
            if (lane >= o) w += t;
        }
        wsum[lane] = w;
    }
    __syncthreads();
    int incl = s + ((wid > 0) ? wsum[wid - 1] : 0);
    if (idx < NN) g_rowptr[idx] = incl - v;         // block-local exclusive
    if (tid == 1023) g_btot[blockIdx.x] = incl;     // block total
}

// (2) scan the 49 block totals (64-thread, 2 warps)
__global__ void scan2_kernel() {
    __shared__ int w0;
    int tid = threadIdx.x;
    int lane = tid & 31, wid = tid >> 5;
    int v = (tid < SCAN_BLKS) ? g_btot[tid] : 0;
    int s = v;
    #pragma unroll
    for (int o = 1; o < 32; o <<= 1) {
        int t = __shfl_up_sync(0xffffffffu, s, o);
        if (lane >= o) s += t;
    }
    if (wid == 0 && lane == 31) w0 = s;
    __syncthreads();
    int incl = s + (wid ? w0 : 0);
    if (tid < SCAN_BLKS) g_boff[tid] = incl - v;
    if (tid == 63) g_rowptr[NN] = incl;
}

// (3) apply block offsets; emit cursor + inv-degree
__global__ void scan3_kernel() {
    int idx = blockIdx.x * 1024 + threadIdx.x;
    if (idx >= NN) return;
    int r = g_rowptr[idx] + g_boff[blockIdx.x];
    g_rowptr[idx] = r;
    g_cursor[idx] = r;
    g_invdeg[idx] = 1.0f / (float)max(g_count[idx], 1);
}

__global__ void fill_kernel() {
    int i = blockIdx.x * blockDim.x + threadIdx.x;
    if (i >= EE) return;
    int d = g_dst[i];
    int p = atomicAdd(&g_cursor[d], 1);
    g_col[p] = g_src[i];
}

// Sort each adjacency list (insertion sort, avg deg 12) so summation order is
// deterministic across calls (atomic fill order is not).
__global__ void sortnb_kernel() {
    int n = blockIdx.x * blockDim.x + threadIdx.x;
    if (n >= NN) return;
    int b = g_rowptr[n], e = g_rowptr[n + 1];
    for (int i = b + 1; i < e; i++) {
        int v = g_col[i];
        int j = i - 1;
        while (j >= b && g_col[j] > v) { g_col[j + 1] = g_col[j]; j--; }
        g_col[j + 1] = v;
    }
}

// ---------------- fused SAGE layer ----------------
// out = relu(mean_nbr(hin) @ Wl^T + hin @ Wr^T + bl)
// Persistent CTAs (2/SM) pull 64-row tiles off an atomic queue. Phase 0
// aggregates the tile's mean rows straight into bf16 hi/lo A-smem (no gmem
// round-trip) and multiplies by Wl; phase 1 loads hin rows and multiplies by Wr.
// bf16x3 split (hi*hi + hi*lo + lo*hi) keeps fp32-level accuracy. While one
// CTA gathers from L2, the co-resident CTA runs MMAs: natural overlap.
__global__ __launch_bounds__(256, 2)
void sage_fused_kernel(const float* __restrict__ hin,
                       const float* __restrict__ Wl, const float* __restrict__ bl,
                       const float* __restrict__ Wr, float* __restrict__ out,
                       int layer)
{
    extern __shared__ char smem[];
    __shared__ int s_tix;
    const u32 sb = smem_u32(smem);
    const int tid = threadIdx.x;
    const int w = tid >> 5;
    const int lane = tid & 31;

    const int wm = w & 1;                  // warp row group: rows wm*32
    const int wn = w >> 1;                 // warp col group: cols wn*32
    const u32 a_lane = (u32)((lane & 15) * 256 + ((lane >> 4) & 1) * 16);
    const u32 b_lane = (u32)(((lane & 7) + ((lane >> 4) & 1) * 8) * 256 + ((lane >> 3) & 1) * 16);

    float2 brg[4];
    #pragma unroll
    for (int ni = 0; ni < 4; ni++)
        brg[ni] = *(const float2*)(bl + wn * 32 + ni * 8 + (lane & 3) * 2);

    while (true) {
        if (tid == 0) s_tix = atomicAdd(&g_tq[layer], 1);
        __syncthreads();
        const int tix = s_tix;
        if (tix >= NT64) break;
        const int row0 = tix * MTILE;

        float acc[8][4];
        #pragma unroll
        for (int i = 0; i < 8; i++)
            #pragma unroll
            for (int q = 0; q < 4; q++) acc[i][q] = 0.f;

        #pragma unroll
        for (int ph = 0; ph < 2; ph++) {
            __syncthreads();   // previous phase/tile smem consumed

            // ---- stage W_phase hi/lo (L2-resident after first tile) ----
            const float* W = ph ? Wr : Wl;
            for (int s = tid; s < 128 * 32; s += 256) {
                int n = s >> 5, kq = s & 31;
                float4 v = *(const float4*)(W + n * 128 + kq * 4);
                uint2 h, l;
                split4(v, h, l);
                u32 off = SW256(n * 256 + kq * 8);
                *(uint2*)(smem + SM_WH + off) = h;
                *(uint2*)(smem + SM_WL + off) = l;
            }

            // ---- fill A tile ----
            if (ph == 0) {
                // aggregate: warp w computes mean for rows w*8 .. w*8+7
                const float4* p = (const float4*)hin;
                for (int i = 0; i < 8; i++) {
                    int r = w * 8 + i;
                    int node = row0 + r;
                    float4 a4 = make_float4(0.f, 0.f, 0.f, 0.f);
                    if (node < NN) {
                        int j = g_rowptr[node], end = g_rowptr[node + 1];
                        for (; j + 2 <= end; j += 2) {
                            float4 v0 = p[g_col[j] * 32 + lane];
                            float4 v1 = p[g_col[j + 1] * 32 + lane];
                            a4.x += v0.x; a4.y += v0.y; a4.z += v0.z; a4.w += v0.w;
                            a4.x += v1.x; a4.y += v1.y; a4.z += v1.z; a4.w += v1.w;
                        }
                        if (j < end) {
                            float4 v0 = p[g_col[j] * 32 + lane];
                            a4.x += v0.x; a4.y += v0.y; a4.z += v0.z; a4.w += v0.w;
                        }
                        float id = g_invdeg[node];
                        a4.x *= id; a4.y *= id; a4.z *= id; a4.w *= id;
                    }
                    uint2 h, l;
                    split4(a4, h, l);
                    u32 off = SW256(r * 256 + lane * 8);
                    *(uint2*)(smem + SM_AH + off) = h;
                    *(uint2*)(smem + SM_AL + off) = l;
                }
            } else {
                for (int s = tid; s < MTILE * 32; s += 256) {
                    int r = s >> 5, kq = s & 31;
                    int gr = row0 + r;
                    float4 v = make_float4(0.f, 0.f, 0.f, 0.f);
                    if (gr < NN) v = *(const float4*)(hin + gr * 128 + kq * 4);
                    uint2 h, l;
                    split4(v, h, l);
                    u32 off = SW256(r * 256 + kq * 8);
                    *(uint2*)(smem + SM_AH + off) = h;
                    *(uint2*)(smem + SM_AL + off) = l;
                }
            }
            __syncthreads();

            // ---- MMA: 8 k16 steps x 3 split terms ----
            const u32 AH = sb + SM_AH, AL = sb + SM_AL;
            const u32 BH = sb + SM_WH, BL = sb + SM_WL;
            #pragma unroll
            for (int ks = 0; ks < 8; ks++) {
                u32 ah[2][4], al[2][4], bh[2][4], blr[2][4];
                u32 aoff = (u32)(wm * 32 * 256) + (u32)(ks * 32) + a_lane;
                #pragma unroll
                for (int mi = 0; mi < 2; mi++)
                    ldm4(ah[mi][0], ah[mi][1], ah[mi][2], ah[mi][3],
                         AH + SW256(aoff + mi * 16 * 256));
                u32 boff = (u32)(wn * 32 * 256) + (u32)(ks * 32) + b_lane;
                #pragma unroll
                for (int g = 0; g < 2; g++)
                    ldm4(bh[g][0], bh[g][1], bh[g][2], bh[g][3],
                         BH + SW256(boff + g * 16 * 256));
                #pragma unroll
                for (int mi = 0; mi < 2; mi++)
                    #pragma unroll
                    for (int ni = 0; ni < 4; ni++)
                        mma_bf16(acc[mi * 4 + ni], ah[mi],
                                 bh[ni >> 1][(ni & 1) * 2], bh[ni >> 1][(ni & 1) * 2 + 1]);
                #pragma unroll
                for (int g = 0; g < 2; g++)
                    ldm4(blr[g][0], blr[g][1], blr[g][2], blr[g][3],
                         BL + SW256(boff + g * 16 * 256));
                #pragma unroll
                for (int mi = 0; mi < 2; mi++)
                    #pragma unroll
                    for (int ni = 0; ni < 4; ni++)
                        mma_bf16(acc[mi * 4 + ni], ah[mi],
                                 blr[ni >> 1][(ni & 1) * 2], blr[ni >> 1][(ni & 1) * 2 + 1]);
                #pragma unroll
                for (int mi = 0; mi < 2; mi++)
                    ldm4(al[mi][0], al[mi][1], al[mi][2], al[mi][3],
                         AL + SW256(aoff + mi * 16 * 256));
                #pragma unroll
                for (int mi = 0; mi < 2; mi++)
                    #pragma unroll
                    for (int ni = 0; ni < 4; ni++)
                        mma_bf16(acc[mi * 4 + ni], al[mi],
                                 bh[ni >> 1][(ni & 1) * 2], bh[ni >> 1][(ni & 1) * 2 + 1]);
            }
        }

        // ---- epilogue: bias + relu + STG ----
        #pragma unroll
        for (int mi = 0; mi < 2; mi++) {
            int r0 = row0 + wm * 32 + mi * 16 + (lane >> 2);
            #pragma unroll
            for (int ni = 0; ni < 4; ni++) {
                const float* d = acc[mi * 4 + ni];
                int c = wn * 32 + ni * 8 + (lane & 3) * 2;
                if (r0 < NN) {
                    float2 o;
                    o.x = fmaxf(d[0] + brg[ni].x, 0.f);
                    o.y = fmaxf(d[1] + brg[ni].y, 0.f);
                    *(float2*)(out + (long)r0 * 128 + c) = o;
                }
                if (r0 + 8 < NN) {
                    float2 o;
                    o.x = fmaxf(d[2] + brg[ni].x, 0.f);
                    o.y = fmaxf(d[3] + brg[ni].y, 0.f);
                    *(float2*)(out + (long)(r0 + 8) * 128 + c) = o;
                }
            }
        }
    }
}

// ---------------- launch ----------------
extern "C" void kernel_launch(void* const* d_in, const int* in_sizes, int n_in,
                              void* d_out, int out_size) {
    const float* x   = (const float*)d_in[0];
    const void*  ei  = d_in[1];
    const float* Wl1 = (const float*)d_in[2];
    const float* bl1 = (const float*)d_in[3];
    const float* Wr1 = (const float*)d_in[4];
    const float* Wl2 = (const float*)d_in[5];
    const float* bl2 = (const float*)d_in[6];
    const float* Wr2 = (const float*)d_in[7];
    const float* Wl3 = (const float*)d_in[8];
    const float* bl3 = (const float*)d_in[9];
    const float* Wr3 = (const float*)d_in[10];
    float* out = (float*)d_out;

    cudaFuncSetAttribute(sage_fused_kernel, cudaFuncAttributeMaxDynamicSharedMemorySize, GEMM_SMEM);

    float *pA, *pB;
    cudaGetSymbolAddress((void**)&pA, g_bufA);
    cudaGetSymbolAddress((void**)&pB, g_bufB);

    // ---- graph preprocessing (deterministic every call) ----
    init_kernel<<<(NN + 255) / 256, 256>>>((const unsigned long long*)ei);
    convert_hist_kernel<<<(EE + 255) / 256, 256>>>(ei);
    scan1_kernel<<<SCAN_BLKS, 1024>>>();
    scan2_kernel<<<1, 64>>>();
    scan3_kernel<<<SCAN_BLKS, 1024>>>();
    fill_kernel<<<(EE + 255) / 256, 256>>>();
    sortnb_kernel<<<(NN + 127) / 128, 128>>>();

    // ---- 3 fused layers ----
    sage_fused_kernel<<<GRID_GEMM, 256, GEMM_SMEM>>>(x,  Wl1, bl1, Wr1, pA, 0);
    sage_fused_kernel<<<GRID_GEMM, 256, GEMM_SMEM>>>(pA, Wl2, bl2, Wr2, pB, 1);
    sage_fused_kernel<<<GRID_GEMM, 256, GEMM_SMEM>>>(pB, Wl3, bl3, Wr3, out, 2);
}

// round 8
// speedup vs baseline: 1.1038x; 1.1038x over previous
#include <cuda_runtime.h>
#include <cuda_bf16.h>

#define NN 50000
#define EE 600000
#define DD 128
#define NTILES 391            // ceil(NN/128)
#define GRID_GEMM 148
#define SCAN_BLKS 49          // ceil(NN/1024)

// ---- gemm smem layout (bytes) ----
// W hi: [128 n][256 k] bf16 = 64KB ; W lo: 64KB ; A: 2 bufs x (hi 16KB + lo 16KB)
#define SM_WH 0
#define SM_WL 65536
#define SM_AB 131072
#define GEMM_SMEM (131072 + 2*32768)   // 196608

// swizzles: XOR row%8 into the 16B-chunk index (conflict-free ldmatrix)
#define SWA(o) ((o) ^ ((((unsigned)(o)) >> 3) & 0x70))   // 128B rows (A tiles)
#define SWW(o) ((o) ^ ((((unsigned)(o)) >> 5) & 0x70))   // 512B rows (W tiles)

typedef unsigned int u32;

// ---------------- scratch ----------------
__device__ float g_bufA[NN * DD];
__device__ float g_bufB[NN * DD];
__device__ float g_mean[NN * DD];
__device__ int   g_src[EE];
__device__ int   g_dst[EE];
__device__ int   g_col[EE];
__device__ int   g_rowptr[NN + 1];
__device__ int   g_cursor[NN];
__device__ int   g_count[NN];
__device__ float g_invdeg[NN];
__device__ int   g_btot[64];
__device__ int   g_boff[64];
__device__ int   g_is64;

// ---------------- helpers ----------------
__device__ __forceinline__ u32 smem_u32(const void* p) {
    u32 a;
    asm("{ .reg .u64 t; cvta.to.shared.u64 t, %1; cvt.u32.u64 %0, t; }" : "=r"(a) : "l"(p));
    return a;
}
__device__ __forceinline__ void ldm4(u32& r0, u32& r1, u32& r2, u32& r3, u32 a) {
    asm volatile("ldmatrix.sync.aligned.m8n8.x4.shared.b16 {%0,%1,%2,%3}, [%4];"
                 : "=r"(r0), "=r"(r1), "=r"(r2), "=r"(r3) : "r"(a));
}
__device__ __forceinline__ void mma_bf16(float* d, const u32* a, u32 b0, u32 b1) {
    asm volatile(
        "mma.sync.aligned.m16n8k16.row.col.f32.bf16.bf16.f32 "
        "{%0,%1,%2,%3}, {%4,%5,%6,%7}, {%8,%9}, {%0,%1,%2,%3};"
        : "+f"(d[0]), "+f"(d[1]), "+f"(d[2]), "+f"(d[3])
        : "r"(a[0]), "r"(a[1]), "r"(a[2]), "r"(a[3]), "r"(b0), "r"(b1));
}
__device__ __forceinline__ u32 pkbf2(float x, float y) {
    __nv_bfloat162 h = __floats2bfloat162_rn(x, y);
    return *(u32*)&h;
}
// split float4 -> packed hi (2x u32) and lo (2x u32)
__device__ __forceinline__ void split4(float4 v, uint2& h, uint2& l) {
    float bx = __bfloat162float(__float2bfloat16_rn(v.x));
    float by = __bfloat162float(__float2bfloat16_rn(v.y));
    float bz = __bfloat162float(__float2bfloat16_rn(v.z));
    float bw = __bfloat162float(__float2bfloat16_rn(v.w));
    h.x = pkbf2(v.x, v.y);           h.y = pkbf2(v.z, v.w);
    l.x = pkbf2(v.x - bx, v.y - by); l.y = pkbf2(v.z - bz, v.w - bw);
}

// ---------------- preprocessing ----------------
__global__ void init_kernel(const unsigned long long* __restrict__ e) {
    int i = blockIdx.x * blockDim.x + threadIdx.x;
    if (i < NN) g_count[i] = 0;
    if (i == 0) {
        int ok = 1;
        #pragma unroll
        for (int t = 0; t < 8; t++)
            if (e[t] >= (unsigned long long)NN) ok = 0;
        g_is64 = ok;
    }
}

__global__ void convert_hist_kernel(const void* __restrict__ eptr) {
    int i = blockIdx.x * blockDim.x + threadIdx.x;
    if (i >= EE) return;
    int s, d;
    if (g_is64) {
        const long long* e = (const long long*)eptr;
        s = (int)e[i]; d = (int)e[EE + i];
    } else {
        const int* e = (const int*)eptr;
        s = e[i]; d = e[EE + i];
    }
    g_src[i] = s;
    g_dst[i] = d;
    atomicAdd(&g_count[d], 1);
}

// multi-block scan: (1) per-block exclusive scan + block totals
__global__ void scan1_kernel() {
    __shared__ int wsum[32];
    int tid = threadIdx.x;
    int lane = tid & 31, wid = tid >> 5;
    int idx = blockIdx.x * 1024 + tid;
    int v = (idx < NN) ? g_count[idx] : 0;
    int s = v;
    #pragma unroll
    for (int o = 1; o < 32; o <<= 1) {
        int t = __shfl_up_sync(0xffffffffu, s, o);
        if (lane >= o) s += t;
    }
    if (lane == 31) wsum[wid] = s;
    __syncthreads();
    if (wid == 0) {
        int w = wsum[lane];
        #pragma unroll
        for (int o = 1; o < 32; o <<= 1) {
            int t = __shfl_up_sync(0xffffffffu, w, o);
            if (lane >= o) w += t;
        }
        wsum[lane] = w;
    }
    __syncthreads();
    int incl = s + ((wid > 0) ? wsum[wid - 1] : 0);
    if (idx < NN) g_rowptr[idx] = incl - v;         // block-local exclusive
    if (tid == 1023) g_btot[blockIdx.x] = incl;     // block total
}

// (2) scan the block totals
__global__ void scan2_kernel() {
    __shared__ int w0;
    int tid = threadIdx.x;
    int lane = tid & 31, wid = tid >> 5;
    int v = (tid < SCAN_BLKS) ? g_btot[tid] : 0;
    int s = v;
    #pragma unroll
    for (int o = 1; o < 32; o <<= 1) {
        int t = __shfl_up_sync(0xffffffffu, s, o);
        if (lane >= o) s += t;
    }
    if (wid == 0 && lane == 31) w0 = s;
    __syncthreads();
    int incl = s + (wid ? w0 : 0);
    if (tid < SCAN_BLKS) g_boff[tid] = incl - v;
    if (tid == 63) g_rowptr[NN] = incl;
}

// (3) apply block offsets; emit cursor + inv-degree
__global__ void scan3_kernel() {
    int idx = blockIdx.x * 1024 + threadIdx.x;
    if (idx >= NN) return;
    int r = g_rowptr[idx] + g_boff[blockIdx.x];
    g_rowptr[idx] = r;
    g_cursor[idx] = r;
    g_invdeg[idx] = 1.0f / (float)max(g_count[idx], 1);
}

__global__ void fill_kernel() {
    int i = blockIdx.x * blockDim.x + threadIdx.x;
    if (i >= EE) return;
    int d = g_dst[i];
    int p = atomicAdd(&g_cursor[d], 1);
    g_col[p] = g_src[i];
}

// Insertion-sort each adjacency list so summation order is deterministic
// across calls (atomic fill order is not). Avg degree 12.
__global__ void sortnb_kernel() {
    int n = blockIdx.x * blockDim.x + threadIdx.x;
    if (n >= NN) return;
    int b = g_rowptr[n], e = g_rowptr[n + 1];
    for (int i = b + 1; i < e; i++) {
        int v = g_col[i];
        int j = i - 1;
        while (j >= b && g_col[j] > v) { g_col[j + 1] = g_col[j]; j--; }
        g_col[j + 1] = v;
    }
}

// ---------------- aggregation ----------------
// One warp per node; lane owns a float4. 25.6 MB table is L2-resident.
__global__ void aggregate_kernel(const float* __restrict__ hin, float* __restrict__ mean) {
    int node = (blockIdx.x * blockDim.x + threadIdx.x) >> 5;
    if (node >= NN) return;
    int lane = threadIdx.x & 31;
    int j = g_rowptr[node], end = g_rowptr[node + 1];
    const float4* p = (const float4*)hin;
    float4 acc = make_float4(0.f, 0.f, 0.f, 0.f);
    for (; j + 2 <= end; j += 2) {
        int s0 = g_col[j], s1 = g_col[j + 1];
        float4 v0 = p[s0 * 32 + lane];
        float4 v1 = p[s1 * 32 + lane];
        acc.x += v0.x; acc.y += v0.y; acc.z += v0.z; acc.w += v0.w;
        acc.x += v1.x; acc.y += v1.y; acc.z += v1.z; acc.w += v1.w;
    }
    if (j < end) {
        float4 v = p[g_col[j] * 32 + lane];
        acc.x += v.x; acc.y += v.y; acc.z += v.z; acc.w += v.w;
    }
    float id = g_invdeg[node];
    acc.x *= id; acc.y *= id; acc.z *= id; acc.w *= id;
    *((float4*)mean + node * 32 + lane) = acc;
}

// ---------------- bf16x3 mma.sync GEMM ----------------
// out = relu([mean|h] @ [Wl;Wr]^T + bl) as one K=256 GEMM.
// 148 persistent CTAs x 512 thr (16 warps, 4/SMSP for latency hiding).
// Warp tile 32x32 (2 m-frags x 4 n-frags). W hi/lo staged once in smem;
// A chunks (128 rows x 64 k) double-buffered, gmem prefetch before mma.
__global__ __launch_bounds__(512, 1)
void gemm_mma_kernel(const float* __restrict__ mean, const float* __restrict__ hin,
                     const float* __restrict__ Wl, const float* __restrict__ bl,
                     const float* __restrict__ Wr, float* __restrict__ out)
{
    extern __shared__ char smem[];
    const u32 sb = smem_u32(smem);
    const int tid = threadIdx.x;
    const int w = tid >> 5;
    const int lane = tid & 31;

    // ---- stage W hi/lo: Wcat[n][k] (k<128: Wl, else Wr), rows 512B, SWW swizzle ----
    for (int s = tid; s < 128 * 64; s += 512) {
        int n = s >> 6, k4 = s & 63;
        int k = k4 * 4;
        float4 v = (k < 128) ? *(const float4*)(Wl + n * 128 + k)
                             : *(const float4*)(Wr + n * 128 + (k - 128));
        uint2 h, l;
        split4(v, h, l);
        u32 off = SWW(n * 512 + k4 * 8);
        *(uint2*)(smem + SM_WH + off) = h;
        *(uint2*)(smem + SM_WL + off) = l;
    }

    // warp grid: 4 row groups x 4 col groups
    const int wr = (w & 3) * 32;           // warp row base in tile
    const int wc = (w >> 2) * 32;          // warp col base
    const u32 a_lane = (u32)((lane & 15) * 128 + ((lane >> 4) & 1) * 16);
    const u32 b_lane = (u32)(((lane & 7) + ((lane >> 4) & 1) * 8) * 512 + ((lane >> 3) & 1) * 16);

    // bias regs for this thread's columns
    float2 brg[4];
    #pragma unroll
    for (int ni = 0; ni < 4; ni++)
        brg[ni] = *(const float2*)(bl + wc + ni * 8 + (lane & 3) * 2);

    __syncthreads();

    for (int tix = blockIdx.x; tix < NTILES; tix += GRID_GEMM) {
        const int row0 = tix * 128;
        float acc[8][4];
        #pragma unroll
        for (int i = 0; i < 8; i++)
            #pragma unroll
            for (int q = 0; q < 4; q++) acc[i][q] = 0.f;

        // stage chunk 0 into buf 0
        float4 v[4];
        {
            #pragma unroll
            for (int j = 0; j < 4; j++) {
                int s = tid + j * 512;
                int row = s >> 4, k4 = s & 15;
                int gr = row0 + row;
                v[j] = make_float4(0.f, 0.f, 0.f, 0.f);
                if (gr < NN) v[j] = *(const float4*)(mean + gr * 128 + k4 * 4);
            }
            #pragma unroll
            for (int j = 0; j < 4; j++) {
                int s = tid + j * 512;
                int row = s >> 4, k4 = s & 15;
                uint2 h, l;
                split4(v[j], h, l);
                u32 off = SWA(row * 128 + k4 * 8);
                *(uint2*)(smem + SM_AB + off) = h;
                *(uint2*)(smem + SM_AB + 16384 + off) = l;
            }
        }
        __syncthreads();

        for (int kc = 0; kc < 4; kc++) {
            const int buf = kc & 1;

            // prefetch next chunk's gmem into regs (hidden behind mma)
            if (kc < 3) {
                const float* src = (kc + 1 < 2) ? mean : hin;
                int kbase = ((kc + 1) & 1) * 64;
                #pragma unroll
                for (int j = 0; j < 4; j++) {
                    int s = tid + j * 512;
                    int row = s >> 4, k4 = s & 15;
                    int gr = row0 + row;
                    v[j] = make_float4(0.f, 0.f, 0.f, 0.f);
                    if (gr < NN) v[j] = *(const float4*)(src + gr * 128 + kbase + k4 * 4);
                }
            }

            // ---- mma over 4 k16 steps, 3 split terms ----
            const u32 AH = sb + SM_AB + buf * 32768;
            const u32 AL = AH + 16384;
            const u32 BH = sb + SM_WH;
            const u32 BL = sb + SM_WL;
            #pragma unroll
            for (int ks = 0; ks < 4; ks++) {
                u32 ah[2][4], al[2][4], bh[2][4], blr[2][4];
                u32 aoff = (u32)(wr * 128) + (u32)(ks * 32) + a_lane;
                #pragma unroll
                for (int mi = 0; mi < 2; mi++)
                    ldm4(ah[mi][0], ah[mi][1], ah[mi][2], ah[mi][3],
                         AH + SWA(aoff + mi * 16 * 128));
                u32 boff = (u32)(wc * 512) + (u32)((kc * 8 + ks * 2) * 16) + b_lane;
                #pragma unroll
                for (int g = 0; g < 2; g++)
                    ldm4(bh[g][0], bh[g][1], bh[g][2], bh[g][3],
                         BH + SWW(boff + g * 16 * 512));
                // hi*hi
                #pragma unroll
                for (int mi = 0; mi < 2; mi++)
                    #pragma unroll
                    for (int ni = 0; ni < 4; ni++)
                        mma_bf16(acc[mi * 4 + ni], ah[mi],
                                 bh[ni >> 1][(ni & 1) * 2], bh[ni >> 1][(ni & 1) * 2 + 1]);
                // hi*lo
                #pragma unroll
                for (int g = 0; g < 2; g++)
                    ldm4(blr[g][0], blr[g][1], blr[g][2], blr[g][3],
                         BL + SWW(boff + g * 16 * 512));
                #pragma unroll
                for (int mi = 0; mi < 2; mi++)
                    #pragma unroll
                    for (int ni = 0; ni < 4; ni++)
                        mma_bf16(acc[mi * 4 + ni], ah[mi],
                                 blr[ni >> 1][(ni & 1) * 2], blr[ni >> 1][(ni & 1) * 2 + 1]);
                // lo*hi
                #pragma unroll
                for (int mi = 0; mi < 2; mi++)
                    ldm4(al[mi][0], al[mi][1], al[mi][2], al[mi][3],
                         AL + SWA(aoff + mi * 16 * 128));
                #pragma unroll
                for (int mi = 0; mi < 2; mi++)
                    #pragma unroll
                    for (int ni = 0; ni < 4; ni++)
                        mma_bf16(acc[mi * 4 + ni], al[mi],
                                 bh[ni >> 1][(ni & 1) * 2], bh[ni >> 1][(ni & 1) * 2 + 1]);
            }

            // store prefetched chunk into other buffer
            if (kc < 3) {
                int nb = buf ^ 1;
                #pragma unroll
                for (int j = 0; j < 4; j++) {
                    int s = tid + j * 512;
                    int row = s >> 4, k4 = s & 15;
                    uint2 h, l;
                    split4(v[j], h, l);
                    u32 off = SWA(row * 128 + k4 * 8);
                    *(uint2*)(smem + SM_AB + nb * 32768 + off) = h;
                    *(uint2*)(smem + SM_AB + nb * 32768 + 16384 + off) = l;
                }
            }
            __syncthreads();
        }

        // ---- epilogue: bias + relu + direct STG ----
        #pragma unroll
        for (int mi = 0; mi < 2; mi++) {
            int r0 = row0 + wr + mi * 16 + (lane >> 2);
            #pragma unroll
            for (int ni = 0; ni < 4; ni++) {
                const float* d = acc[mi * 4 + ni];
                int c = wc + ni * 8 + (lane & 3) * 2;
                if (r0 < NN) {
                    float2 o;
                    o.x = fmaxf(d[0] + brg[ni].x, 0.f);
                    o.y = fmaxf(d[1] + brg[ni].y, 0.f);
                    *(float2*)(out + (long)r0 * 128 + c) = o;
                }
                if (r0 + 8 < NN) {
                    float2 o;
                    o.x = fmaxf(d[2] + brg[ni].x, 0.f);
                    o.y = fmaxf(d[3] + brg[ni].y, 0.f);
                    *(float2*)(out + (long)(r0 + 8) * 128 + c) = o;
                }
            }
        }
        __syncthreads();   // tile done before next chunk0 staging overwrites buf0
    }
}

// ---------------- launch ----------------
extern "C" void kernel_launch(void* const* d_in, const int* in_sizes, int n_in,
                              void* d_out, int out_size) {
    const float* x   = (const float*)d_in[0];
    const void*  ei  = d_in[1];
    const float* Wl1 = (const float*)d_in[2];
    const float* bl1 = (const float*)d_in[3];
    const float* Wr1 = (const float*)d_in[4];
    const float* Wl2 = (const float*)d_in[5];
    const float* bl2 = (const float*)d_in[6];
    const float* Wr2 = (const float*)d_in[7];
    const float* Wl3 = (const float*)d_in[8];
    const float* bl3 = (const float*)d_in[9];
    const float* Wr3 = (const float*)d_in[10];
    float* out = (float*)d_out;

    cudaFuncSetAttribute(gemm_mma_kernel, cudaFuncAttributeMaxDynamicSharedMemorySize, GEMM_SMEM);

    float *pA, *pB, *pM;
    cudaGetSymbolAddress((void**)&pA, g_bufA);
    cudaGetSymbolAddress((void**)&pB, g_bufB);
    cudaGetSymbolAddress((void**)&pM, g_mean);

    // ---- graph preprocessing (deterministic every call) ----
    init_kernel<<<(NN + 255) / 256, 256>>>((const unsigned long long*)ei);
    convert_hist_kernel<<<(EE + 255) / 256, 256>>>(ei);
    scan1_kernel<<<SCAN_BLKS, 1024>>>();
    scan2_kernel<<<1, 64>>>();
    scan3_kernel<<<SCAN_BLKS, 1024>>>();
    fill_kernel<<<(EE + 255) / 256, 256>>>();
    sortnb_kernel<<<(NN + 127) / 128, 128>>>();

    const int agg_blocks = (NN * 32 + 255) / 256;

    // ---- layer 1 ----
    aggregate_kernel<<<agg_blocks, 256>>>(x, pM);
    gemm_mma_kernel<<<GRID_GEMM, 512, GEMM_SMEM>>>(pM, x, Wl1, bl1, Wr1, pA);
    // ---- layer 2 ----
    aggregate_kernel<<<agg_blocks, 256>>>(pA, pM);
    gemm_mma_kernel<<<GRID_GEMM, 512, GEMM_SMEM>>>(pM, pA, Wl2, bl2, Wr2, pB);
    // ---- layer 3 ----
    aggregate_kernel<<<agg_blocks, 256>>>(pB, pM);
    gemm_mma_kernel<<<GRID_GEMM, 512, GEMM_SMEM>>>(pM, pB, Wl3, bl3, Wr3, out);
}